// round 14
// baseline (speedup 1.0000x reference)
#include <cuda_runtime.h>

// out[b,i,j,c1,c2,k]: k=0 -> x[b,i,c1,c2], k=1 -> x[b,j,c1,c2]
// B=64, GS=96, C=8. Tile (b,i,j) = 128 floats, interleaved (xi[e], xj[e]).
//
// FINAL (roofline lock-in): this problem is a 302 MB pure write stream;
// steady-state it runs at ~6.4 TB/s to HBM (~80% of spec), the DRAM-write
// ceiling. Verified invariant across STG/persistent/TMA/paired-tile
// variants (R4-R11, all 47.3-47.6 us). Best-measured config:
//   - one CTA per (b,i), grid 6144, 256 thr, 32 regs, 8 CTA/SM
//   - xi float4 hoisted to registers (loop-invariant over j)
//   - all 6 xj LDG.128 issued up-front (MLP=6, L2-resident input)
//   - 6 back-to-back st.global.cs.v8.f32 (256-bit, evict-first streaming):
//     1024 B contiguous per warp-store, full-line writes, no RFO traffic.

static constexpr int GS = 96;
static constexpr int ROW = 64;  // 8*8 floats per (b,g) block

__global__ void __launch_bounds__(256)
combo_kernel(const float* __restrict__ x, float* __restrict__ out)
{
    const int bi = blockIdx.x;            // b*GS + i
    const int t = threadIdx.x;
    const int lane16 = t & 15;            // element-group within tile
    const int jbase  = t >> 4;            // 0..15

    // xi: this thread's 4 elements of x[b,i], loop-invariant
    const float4 a = *reinterpret_cast<const float4*>(x + bi * ROW + lane16 * 4);

    const float* xb = x + (bi / GS) * GS * ROW;          // x[b, 0]
    float* outb = out + (size_t)bi * GS * 128;           // out[b, i, 0]

    // Preload all 6 xj vectors (independent loads, MLP=6)
    float4 c[6];
#pragma unroll
    for (int it = 0; it < 6; ++it) {
        const int j = jbase + it * 16;
        c[it] = *reinterpret_cast<const float4*>(xb + j * ROW + lane16 * 4);
    }

    // 6 back-to-back 256-bit streaming stores
#pragma unroll
    for (int it = 0; it < 6; ++it) {
        const int j = jbase + it * 16;
        float* p = outb + j * 128 + lane16 * 8;
        asm volatile(
            "st.global.cs.v8.f32 [%0], {%1,%2,%3,%4,%5,%6,%7,%8};" ::
            "l"(p),
            "f"(a.x), "f"(c[it].x), "f"(a.y), "f"(c[it].y),
            "f"(a.z), "f"(c[it].z), "f"(a.w), "f"(c[it].w)
            : "memory");
    }
}

extern "C" void kernel_launch(void* const* d_in, const int* in_sizes, int n_in,
                              void* d_out, int out_size)
{
    const float* x = (const float*)d_in[0];
    float* out = (float*)d_out;

    // one block per (b, i): 64*96 = 6144 blocks
    combo_kernel<<<64 * GS, 256>>>(x, out);
}